// round 6
// baseline (speedup 1.0000x reference)
#include <cuda_runtime.h>

#define NB 8
#define NT 256   // TE == TD
#define ND 256
#define NU 256

// Scratch (no allocations allowed in kernel_launch)
__device__ float g_ae[NB*NT*NU];      // (B*TE, U)
__device__ float g_ad[NB*NT*NU];      // (B*TD, U)
__device__ float g_alphas[NB*NT*NT];  // (B, TD, TE)
__device__ float g_maxmu[NB*NT];      // (B, TD)
__device__ float g_hhat[NB*ND];       // (B, D)

__device__ __forceinline__ float tanh_fast(float x){
    float y; asm("tanh.approx.f32 %0, %1;" : "=f"(y) : "f"(x)); return y;
}

// ---------------------------------------------------------------------------
// K1 v2: ae = en @ w_en, ad = de @ w_de.
// grid 256: blocks [0,128) -> ae, [128,256) -> ad. Each block: 16 rows.
// 256 threads: ty = tid>>6 -> 4 rows (ty*4..ty*4+3), tx = tid&63 -> 4 u's.
// 16 FMA per LDG.128 of w -> FMA-bound (~8 cyc/warp-iter).
// ---------------------------------------------------------------------------
__global__ void __launch_bounds__(256) k1_proj(
    const float* __restrict__ en, const float* __restrict__ de,
    const float* __restrict__ w_en, const float* __restrict__ w_de)
{
    __shared__ float s_in[16*ND];
    int bb = blockIdx.x;
    bool isA = bb < 128;
    int rb = (isA ? bb : bb - 128) * 16;            // row base in [0,2048)
    const float* in = isA ? en : de;
    const float* w  = isA ? w_en : w_de;
    float* out      = isA ? g_ae : g_ad;

    // cooperative load of 16 input rows (4096 floats = 1024 float4)
    {
        const float4* in4 = (const float4*)(in + rb*ND);
        float4* s4 = (float4*)s_in;
        #pragma unroll
        for (int i = 0; i < 4; i++)
            s4[threadIdx.x + i*256] = in4[threadIdx.x + i*256];
    }
    __syncthreads();

    int tx = threadIdx.x & 63;        // u-group of 4
    int ty = threadIdx.x >> 6;        // 0..3 -> rows ty*4..ty*4+3
    const float* srow = s_in + ty*4*ND;
    const float4* w4 = (const float4*)w;

    float4 a0 = make_float4(0.f,0.f,0.f,0.f);
    float4 a1 = a0, a2 = a0, a3 = a0;

    #pragma unroll 4
    for (int d = 0; d < ND; d++){
        float4 wv = w4[d*64 + tx];
        float x0 = srow[0*ND + d];
        float x1 = srow[1*ND + d];
        float x2 = srow[2*ND + d];
        float x3 = srow[3*ND + d];
        a0.x = fmaf(x0, wv.x, a0.x); a0.y = fmaf(x0, wv.y, a0.y);
        a0.z = fmaf(x0, wv.z, a0.z); a0.w = fmaf(x0, wv.w, a0.w);
        a1.x = fmaf(x1, wv.x, a1.x); a1.y = fmaf(x1, wv.y, a1.y);
        a1.z = fmaf(x1, wv.z, a1.z); a1.w = fmaf(x1, wv.w, a1.w);
        a2.x = fmaf(x2, wv.x, a2.x); a2.y = fmaf(x2, wv.y, a2.y);
        a2.z = fmaf(x2, wv.z, a2.z); a2.w = fmaf(x2, wv.w, a2.w);
        a3.x = fmaf(x3, wv.x, a3.x); a3.y = fmaf(x3, wv.y, a3.y);
        a3.z = fmaf(x3, wv.z, a3.z); a3.w = fmaf(x3, wv.w, a3.w);
    }

    int r = rb + ty*4;
    ((float4*)(out + (r+0)*NU))[tx] = a0;
    ((float4*)(out + (r+1)*NU))[tx] = a1;
    ((float4*)(out + (r+2)*NU))[tx] = a2;
    ((float4*)(out + (r+3)*NU))[tx] = a3;
}

// ---------------------------------------------------------------------------
// K2: mu[b,s,t] = sum_u tanh(ad[b,s,u] + ae[b,t,u]) * nu[u]
//     then rowwise softmax over t -> g_alphas; rowmax -> g_maxmu.
// grid 512: block = (b, 4 consecutive s rows). 256 threads = 8 warps.
// (unchanged — sits at the MUFU throughput floor)
// ---------------------------------------------------------------------------
__global__ void __launch_bounds__(256) k2_mu(const float* __restrict__ nu)
{
    __shared__ float s_mu[4][256];
    int blk  = blockIdx.x;
    int b    = blk >> 6;              // 64 blocks per batch
    int s0   = (blk & 63) * 4;
    int lane = threadIdx.x & 31;
    int w    = threadIdx.x >> 5;

    float nur[8], adr0[8], adr1[8], adr2[8], adr3[8];
    #pragma unroll
    for (int k = 0; k < 8; k++) nur[k] = nu[lane + 32*k];
    const float* adb = g_ad + (b*NT + s0)*NU;
    #pragma unroll
    for (int k = 0; k < 8; k++){
        int u = lane + 32*k;
        adr0[k] = adb[0*NU + u];
        adr1[k] = adb[1*NU + u];
        adr2[k] = adb[2*NU + u];
        adr3[k] = adb[3*NU + u];
    }
    const float* aeb = g_ae + b*NT*NU;

    for (int ti = 0; ti < 32; ti++){
        int t = ti*8 + w;
        const float* aet = aeb + t*NU;
        float a0=0.f, a1=0.f, a2=0.f, a3=0.f;
        #pragma unroll
        for (int k = 0; k < 8; k++){
            float a = aet[lane + 32*k];
            a0 = fmaf(tanh_fast(adr0[k] + a), nur[k], a0);
            a1 = fmaf(tanh_fast(adr1[k] + a), nur[k], a1);
            a2 = fmaf(tanh_fast(adr2[k] + a), nur[k], a2);
            a3 = fmaf(tanh_fast(adr3[k] + a), nur[k], a3);
        }
        #pragma unroll
        for (int off = 16; off; off >>= 1){
            a0 += __shfl_xor_sync(0xffffffffu, a0, off);
            a1 += __shfl_xor_sync(0xffffffffu, a1, off);
            a2 += __shfl_xor_sync(0xffffffffu, a2, off);
            a3 += __shfl_xor_sync(0xffffffffu, a3, off);
        }
        if (lane == 0){
            s_mu[0][t] = a0; s_mu[1][t] = a1;
            s_mu[2][t] = a2; s_mu[3][t] = a3;
        }
    }
    __syncthreads();

    // softmax over t for each of the 4 s rows; warps 0..3 each own one row
    if (w < 4){
        int s = w;
        float v[8];
        float m = -1e30f;
        #pragma unroll
        for (int j = 0; j < 8; j++){ v[j] = s_mu[s][lane + 32*j]; m = fmaxf(m, v[j]); }
        #pragma unroll
        for (int off = 16; off; off >>= 1) m = fmaxf(m, __shfl_xor_sync(0xffffffffu, m, off));
        float sum = 0.f;
        #pragma unroll
        for (int j = 0; j < 8; j++){ v[j] = __expf(v[j] - m); sum += v[j]; }
        #pragma unroll
        for (int off = 16; off; off >>= 1) sum += __shfl_xor_sync(0xffffffffu, sum, off);
        float inv = 1.0f / sum;
        float* arow = g_alphas + (b*NT + s0 + s)*NT;
        #pragma unroll
        for (int j = 0; j < 8; j++) arow[lane + 32*j] = v[j] * inv;
        if (lane == 0) g_maxmu[b*NT + s0 + s] = m;
    }
}

// ---------------------------------------------------------------------------
// K3: max_alphas = softmax over s of max_mu[b,:]; h_hat[b,d] = sum_s de*ma.
// grid NB, 256 threads. (unchanged, ~3us)
// ---------------------------------------------------------------------------
__global__ void __launch_bounds__(256) k3_hhat(const float* __restrict__ de)
{
    __shared__ float s_ma[256];
    __shared__ float s_red[8];
    int b = blockIdx.x;
    int tid = threadIdx.x, lane = tid & 31, w = tid >> 5;

    float v = g_maxmu[b*NT + tid];
    float m = v;
    #pragma unroll
    for (int off = 16; off; off >>= 1) m = fmaxf(m, __shfl_xor_sync(0xffffffffu, m, off));
    if (lane == 0) s_red[w] = m;
    __syncthreads();
    m = s_red[0];
    #pragma unroll
    for (int i = 1; i < 8; i++) m = fmaxf(m, s_red[i]);
    __syncthreads();

    float e = __expf(v - m);
    float psum = e;
    #pragma unroll
    for (int off = 16; off; off >>= 1) psum += __shfl_xor_sync(0xffffffffu, psum, off);
    if (lane == 0) s_red[w] = psum;
    __syncthreads();
    float tot = 0.f;
    #pragma unroll
    for (int i = 0; i < 8; i++) tot += s_red[i];
    s_ma[tid] = e / tot;
    __syncthreads();

    int d = tid;
    const float* deb = de + b*NT*ND;
    float acc = 0.f;
    #pragma unroll 4
    for (int s = 0; s < NT; s++) acc = fmaf(deb[s*ND + d], s_ma[s], acc);
    g_hhat[b*ND + d] = acc;
}

// ---------------------------------------------------------------------------
// K4 v2: sum_en[b,s,:] = alphas[b,s,:] @ en[b]; assemble output concat.
// grid 128: block = (b, 16 s rows). 256 threads: ty=tid>>6 -> 4 s rows,
// tx=tid&63 -> 4 d's (float4). 16 FMA per LDG.128 of en; alphas tile in
// smem read as scalar broadcasts. FMA-bound.
// ---------------------------------------------------------------------------
__global__ void __launch_bounds__(256) k4_out(
    const float* __restrict__ en, const float* __restrict__ de,
    float* __restrict__ out)
{
    __shared__ float s_a[16*NT];   // [s][t]
    int blk = blockIdx.x;
    int b   = blk >> 4;
    int s0  = (blk & 15) * 16;

    // cooperative load of 16 alpha rows (4096 floats = 1024 float4)
    {
        const float4* ab = (const float4*)(g_alphas + (b*NT + s0)*NT);
        float4* sa4 = (float4*)s_a;
        #pragma unroll
        for (int i = 0; i < 4; i++)
            sa4[threadIdx.x + i*256] = ab[threadIdx.x + i*256];
    }
    __syncthreads();

    int tx = threadIdx.x & 63;        // d-group of 4
    int ty = threadIdx.x >> 6;        // 0..3 -> s rows ty*4..ty*4+3
    const float* arow = s_a + ty*4*NT;
    const float4* en4 = (const float4*)(en + b*NT*ND);

    float4 c[4];
    #pragma unroll
    for (int j = 0; j < 4; j++) c[j] = make_float4(0.f,0.f,0.f,0.f);

    #pragma unroll 4
    for (int t = 0; t < NT; t++){
        float4 e = en4[t*64 + tx];
        float x0 = arow[0*NT + t];
        float x1 = arow[1*NT + t];
        float x2 = arow[2*NT + t];
        float x3 = arow[3*NT + t];
        c[0].x = fmaf(x0, e.x, c[0].x); c[0].y = fmaf(x0, e.y, c[0].y);
        c[0].z = fmaf(x0, e.z, c[0].z); c[0].w = fmaf(x0, e.w, c[0].w);
        c[1].x = fmaf(x1, e.x, c[1].x); c[1].y = fmaf(x1, e.y, c[1].y);
        c[1].z = fmaf(x1, e.z, c[1].z); c[1].w = fmaf(x1, e.w, c[1].w);
        c[2].x = fmaf(x2, e.x, c[2].x); c[2].y = fmaf(x2, e.y, c[2].y);
        c[2].z = fmaf(x2, e.z, c[2].z); c[2].w = fmaf(x2, e.w, c[2].w);
        c[3].x = fmaf(x3, e.x, c[3].x); c[3].y = fmaf(x3, e.y, c[3].y);
        c[3].z = fmaf(x3, e.z, c[3].z); c[3].w = fmaf(x3, e.w, c[3].w);
    }

    float4 hh = ((const float4*)(g_hhat + b*ND))[tx];

    #pragma unroll
    for (int j = 0; j < 4; j++){
        int row = b*NT + s0 + ty*4 + j;
        float4 dv = ((const float4*)(de + row*ND))[tx];
        float4 cs = c[j];
        float4* o = (float4*)(out + (size_t)row * (4*ND));
        o[0*64 + tx] = dv;
        o[1*64 + tx] = cs;
        o[2*64 + tx] = make_float4(dv.x*cs.x, dv.y*cs.y, dv.z*cs.z, dv.w*cs.w);
        o[3*64 + tx] = make_float4(dv.x*hh.x, dv.y*hh.y, dv.z*hh.z, dv.w*hh.w);
    }
}

extern "C" void kernel_launch(void* const* d_in, const int* in_sizes, int n_in,
                              void* d_out, int out_size)
{
    const float* en   = (const float*)d_in[0];
    const float* de   = (const float*)d_in[1];
    const float* w_en = (const float*)d_in[2];
    const float* w_de = (const float*)d_in[3];
    const float* nu   = (const float*)d_in[4];
    float* out = (float*)d_out;

    k1_proj<<<256, 256>>>(en, de, w_en, w_de);
    k2_mu  <<<512, 256>>>(nu);
    k3_hhat<<<NB,  256>>>(de);
    k4_out <<<128, 256>>>(en, de, out);
}

// round 8
// speedup vs baseline: 1.1227x; 1.1227x over previous
#include <cuda_runtime.h>

#define NB 8
#define NT 256   // TE == TD
#define ND 256
#define NU 256

// Scratch (no allocations allowed in kernel_launch)
__device__ float g_ae[NB*NT*NU];      // (B*TE, U)
__device__ float g_ad[NB*NT*NU];      // (B*TD, U)
__device__ float g_alphas[NB*NT*NT];  // (B, TD, TE)
__device__ float g_maxmu[NB*NT];      // (B, TD)
__device__ float g_hhat[NB*ND];       // (B, D)

__device__ __forceinline__ float tanh_fast(float x){
    float y; asm("tanh.approx.f32 %0, %1;" : "=f"(y) : "f"(x)); return y;
}

// ---------------------------------------------------------------------------
// K1 v2 (unchanged, ~13us): ae = en @ w_en, ad = de @ w_de.
// grid 256: blocks [0,128) -> ae, [128,256) -> ad. Each block: 16 rows.
// ---------------------------------------------------------------------------
__global__ void __launch_bounds__(256) k1_proj(
    const float* __restrict__ en, const float* __restrict__ de,
    const float* __restrict__ w_en, const float* __restrict__ w_de)
{
    __shared__ float s_in[16*ND];
    int bb = blockIdx.x;
    bool isA = bb < 128;
    int rb = (isA ? bb : bb - 128) * 16;            // row base in [0,2048)
    const float* in = isA ? en : de;
    const float* w  = isA ? w_en : w_de;
    float* out      = isA ? g_ae : g_ad;

    {
        const float4* in4 = (const float4*)(in + rb*ND);
        float4* s4 = (float4*)s_in;
        #pragma unroll
        for (int i = 0; i < 4; i++)
            s4[threadIdx.x + i*256] = in4[threadIdx.x + i*256];
    }
    __syncthreads();

    int tx = threadIdx.x & 63;        // u-group of 4
    int ty = threadIdx.x >> 6;        // 0..3 -> rows ty*4..ty*4+3
    const float* srow = s_in + ty*4*ND;
    const float4* w4 = (const float4*)w;

    float4 a0 = make_float4(0.f,0.f,0.f,0.f);
    float4 a1 = a0, a2 = a0, a3 = a0;

    #pragma unroll 4
    for (int d = 0; d < ND; d++){
        float4 wv = w4[d*64 + tx];
        float x0 = srow[0*ND + d];
        float x1 = srow[1*ND + d];
        float x2 = srow[2*ND + d];
        float x3 = srow[3*ND + d];
        a0.x = fmaf(x0, wv.x, a0.x); a0.y = fmaf(x0, wv.y, a0.y);
        a0.z = fmaf(x0, wv.z, a0.z); a0.w = fmaf(x0, wv.w, a0.w);
        a1.x = fmaf(x1, wv.x, a1.x); a1.y = fmaf(x1, wv.y, a1.y);
        a1.z = fmaf(x1, wv.z, a1.z); a1.w = fmaf(x1, wv.w, a1.w);
        a2.x = fmaf(x2, wv.x, a2.x); a2.y = fmaf(x2, wv.y, a2.y);
        a2.z = fmaf(x2, wv.z, a2.z); a2.w = fmaf(x2, wv.w, a2.w);
        a3.x = fmaf(x3, wv.x, a3.x); a3.y = fmaf(x3, wv.y, a3.y);
        a3.z = fmaf(x3, wv.z, a3.z); a3.w = fmaf(x3, wv.w, a3.w);
    }

    int r = rb + ty*4;
    ((float4*)(out + (r+0)*NU))[tx] = a0;
    ((float4*)(out + (r+1)*NU))[tx] = a1;
    ((float4*)(out + (r+2)*NU))[tx] = a2;
    ((float4*)(out + (r+3)*NU))[tx] = a3;
}

// ---------------------------------------------------------------------------
// K2 (unchanged — MUFU throughput floor ~31us)
// ---------------------------------------------------------------------------
__global__ void __launch_bounds__(256) k2_mu(const float* __restrict__ nu)
{
    __shared__ float s_mu[4][256];
    int blk  = blockIdx.x;
    int b    = blk >> 6;              // 64 blocks per batch
    int s0   = (blk & 63) * 4;
    int lane = threadIdx.x & 31;
    int w    = threadIdx.x >> 5;

    float nur[8], adr0[8], adr1[8], adr2[8], adr3[8];
    #pragma unroll
    for (int k = 0; k < 8; k++) nur[k] = nu[lane + 32*k];
    const float* adb = g_ad + (b*NT + s0)*NU;
    #pragma unroll
    for (int k = 0; k < 8; k++){
        int u = lane + 32*k;
        adr0[k] = adb[0*NU + u];
        adr1[k] = adb[1*NU + u];
        adr2[k] = adb[2*NU + u];
        adr3[k] = adb[3*NU + u];
    }
    const float* aeb = g_ae + b*NT*NU;

    for (int ti = 0; ti < 32; ti++){
        int t = ti*8 + w;
        const float* aet = aeb + t*NU;
        float a0=0.f, a1=0.f, a2=0.f, a3=0.f;
        #pragma unroll
        for (int k = 0; k < 8; k++){
            float a = aet[lane + 32*k];
            a0 = fmaf(tanh_fast(adr0[k] + a), nur[k], a0);
            a1 = fmaf(tanh_fast(adr1[k] + a), nur[k], a1);
            a2 = fmaf(tanh_fast(adr2[k] + a), nur[k], a2);
            a3 = fmaf(tanh_fast(adr3[k] + a), nur[k], a3);
        }
        #pragma unroll
        for (int off = 16; off; off >>= 1){
            a0 += __shfl_xor_sync(0xffffffffu, a0, off);
            a1 += __shfl_xor_sync(0xffffffffu, a1, off);
            a2 += __shfl_xor_sync(0xffffffffu, a2, off);
            a3 += __shfl_xor_sync(0xffffffffu, a3, off);
        }
        if (lane == 0){
            s_mu[0][t] = a0; s_mu[1][t] = a1;
            s_mu[2][t] = a2; s_mu[3][t] = a3;
        }
    }
    __syncthreads();

    if (w < 4){
        int s = w;
        float v[8];
        float m = -1e30f;
        #pragma unroll
        for (int j = 0; j < 8; j++){ v[j] = s_mu[s][lane + 32*j]; m = fmaxf(m, v[j]); }
        #pragma unroll
        for (int off = 16; off; off >>= 1) m = fmaxf(m, __shfl_xor_sync(0xffffffffu, m, off));
        float sum = 0.f;
        #pragma unroll
        for (int j = 0; j < 8; j++){ v[j] = __expf(v[j] - m); sum += v[j]; }
        #pragma unroll
        for (int off = 16; off; off >>= 1) sum += __shfl_xor_sync(0xffffffffu, sum, off);
        float inv = 1.0f / sum;
        float* arow = g_alphas + (b*NT + s0 + s)*NT;
        #pragma unroll
        for (int j = 0; j < 8; j++) arow[lane + 32*j] = v[j] * inv;
        if (lane == 0) g_maxmu[b*NT + s0 + s] = m;
    }
}

// ---------------------------------------------------------------------------
// K3 (unchanged, ~3us)
// ---------------------------------------------------------------------------
__global__ void __launch_bounds__(256) k3_hhat(const float* __restrict__ de)
{
    __shared__ float s_ma[256];
    __shared__ float s_red[8];
    int b = blockIdx.x;
    int tid = threadIdx.x, lane = tid & 31, w = tid >> 5;

    float v = g_maxmu[b*NT + tid];
    float m = v;
    #pragma unroll
    for (int off = 16; off; off >>= 1) m = fmaxf(m, __shfl_xor_sync(0xffffffffu, m, off));
    if (lane == 0) s_red[w] = m;
    __syncthreads();
    m = s_red[0];
    #pragma unroll
    for (int i = 1; i < 8; i++) m = fmaxf(m, s_red[i]);
    __syncthreads();

    float e = __expf(v - m);
    float psum = e;
    #pragma unroll
    for (int off = 16; off; off >>= 1) psum += __shfl_xor_sync(0xffffffffu, psum, off);
    if (lane == 0) s_red[w] = psum;
    __syncthreads();
    float tot = 0.f;
    #pragma unroll
    for (int i = 0; i < 8; i++) tot += s_red[i];
    s_ma[tid] = e / tot;
    __syncthreads();

    int d = tid;
    const float* deb = de + b*NT*ND;
    float acc = 0.f;
    #pragma unroll 4
    for (int s = 0; s < NT; s++) acc = fmaf(deb[s*ND + d], s_ma[s], acc);
    g_hhat[b*ND + d] = acc;
}

// ---------------------------------------------------------------------------
// K4 v3: sum_en[b,s,:] = alphas[b,s,:] @ en[b]; assemble output concat.
// grid 128: block = (b, 16 s rows). Same 4s x 4d register tile as v2
// (16 FMA per 16B of en), but en is staged through double-buffered SMEM:
// cooperative bulk LDG of the next 8-t stage (high MLP, overlapped with a
// full stage of FMA) -> compute reads SMEM (29-cyc lat, conflict-free).
// FMA-issue-bound: ~16K cyc ~ 9us.
// ---------------------------------------------------------------------------
__global__ void __launch_bounds__(256) k4_out(
    const float* __restrict__ en, const float* __restrict__ de,
    float* __restrict__ out)
{
    __shared__ float  s_a[16*NT];        // alphas tile [s][t], 16KB
    __shared__ float4 s_en[2][512];      // 2 stages x (8 t-rows x 64 float4), 16KB
    int blk = blockIdx.x;
    int b   = blk >> 4;
    int s0  = (blk & 15) * 16;
    int tid = threadIdx.x;

    // cooperative load of 16 alpha rows (4096 floats = 1024 float4)
    {
        const float4* ab = (const float4*)(g_alphas + (b*NT + s0)*NT);
        float4* sa4 = (float4*)s_a;
        #pragma unroll
        for (int i = 0; i < 4; i++)
            sa4[tid + i*256] = ab[tid + i*256];
    }

    const float4* en4 = (const float4*)(en + b*NT*ND);

    // prologue: stage 0 (t rows 0..7 = flat float4 indices 0..511)
    float4 p0 = en4[tid];
    float4 p1 = en4[tid + 256];
    s_en[0][tid]       = p0;
    s_en[0][tid + 256] = p1;
    __syncthreads();

    int tx = tid & 63;        // d-group of 4
    int ty = tid >> 6;        // 0..3 -> s rows ty*4..ty*4+3
    const float* arow = s_a + ty*4*NT;

    float4 c[4];
    #pragma unroll
    for (int j = 0; j < 4; j++) c[j] = make_float4(0.f,0.f,0.f,0.f);

    for (int st = 0; st < 32; st++){
        int cur = st & 1;
        // prefetch next stage into registers (bulk LDG, overlapped with FMAs)
        if (st < 31){
            p0 = en4[(st+1)*512 + tid];
            p1 = en4[(st+1)*512 + tid + 256];
        }
        // compute 8 t's of this stage from SMEM
        #pragma unroll
        for (int j = 0; j < 8; j++){
            int t = st*8 + j;
            float4 e = s_en[cur][j*64 + tx];
            float x0 = arow[0*NT + t];
            float x1 = arow[1*NT + t];
            float x2 = arow[2*NT + t];
            float x3 = arow[3*NT + t];
            c[0].x = fmaf(x0, e.x, c[0].x); c[0].y = fmaf(x0, e.y, c[0].y);
            c[0].z = fmaf(x0, e.z, c[0].z); c[0].w = fmaf(x0, e.w, c[0].w);
            c[1].x = fmaf(x1, e.x, c[1].x); c[1].y = fmaf(x1, e.y, c[1].y);
            c[1].z = fmaf(x1, e.z, c[1].z); c[1].w = fmaf(x1, e.w, c[1].w);
            c[2].x = fmaf(x2, e.x, c[2].x); c[2].y = fmaf(x2, e.y, c[2].y);
            c[2].z = fmaf(x2, e.z, c[2].z); c[2].w = fmaf(x2, e.w, c[2].w);
            c[3].x = fmaf(x3, e.x, c[3].x); c[3].y = fmaf(x3, e.y, c[3].y);
            c[3].z = fmaf(x3, e.z, c[3].z); c[3].w = fmaf(x3, e.w, c[3].w);
        }
        // publish next stage (different buffer than the one just read;
        // the barrier makes it visible before stage st+1's compute)
        if (st < 31){
            int nxt = cur ^ 1;
            s_en[nxt][tid]       = p0;
            s_en[nxt][tid + 256] = p1;
        }
        __syncthreads();
    }

    float4 hh = ((const float4*)(g_hhat + b*ND))[tx];

    #pragma unroll
    for (int j = 0; j < 4; j++){
        int row = b*NT + s0 + ty*4 + j;
        float4 dv = ((const float4*)(de + row*ND))[tx];
        float4 cs = c[j];
        float4* o = (float4*)(out + (size_t)row * (4*ND));
        o[0*64 + tx] = dv;
        o[1*64 + tx] = cs;
        o[2*64 + tx] = make_float4(dv.x*cs.x, dv.y*cs.y, dv.z*cs.z, dv.w*cs.w);
        o[3*64 + tx] = make_float4(dv.x*hh.x, dv.y*hh.y, dv.z*hh.z, dv.w*hh.w);
    }
}

extern "C" void kernel_launch(void* const* d_in, const int* in_sizes, int n_in,
                              void* d_out, int out_size)
{
    const float* en   = (const float*)d_in[0];
    const float* de   = (const float*)d_in[1];
    const float* w_en = (const float*)d_in[2];
    const float* w_de = (const float*)d_in[3];
    const float* nu   = (const float*)d_in[4];
    float* out = (float*)d_out;

    k1_proj<<<256, 256>>>(en, de, w_en, w_de);
    k2_mu  <<<512, 256>>>(nu);
    k3_hhat<<<NB,  256>>>(de);
    k4_out <<<128, 256>>>(en, de, out);
}

// round 9
// speedup vs baseline: 1.2005x; 1.0693x over previous
#include <cuda_runtime.h>

#define NB 8
#define NT 256   // TE == TD
#define ND 256
#define NU 256

// Scratch (no allocations allowed in kernel_launch)
__device__ float g_ae[NB*NT*NU];      // (B*TE, U)
__device__ float g_ad[NB*NT*NU];      // (B*TD, U)
__device__ float g_alphas[NB*NT*NT];  // (B, TD, TE)
__device__ float g_maxmu[NB*NT];      // (B, TD)
__device__ float g_hhat[NB*ND];       // (B, D)

__device__ __forceinline__ float tanh_fast(float x){
    float y; asm("tanh.approx.f32 %0, %1;" : "=f"(y) : "f"(x)); return y;
}

// ---------------------------------------------------------------------------
// K1 v3: ae = en @ w_en, ad = de @ w_de.
// grid 128: blocks [0,64) -> ae, [64,128) -> ad. Each block: 32 rows.
// 512 threads (4 warps/SMSP). w staged through double-buffered SMEM in
// 16-d stages; input rows in SMEM. Each thread: 4 rows x 4 u = 16 FMA per
// staged w float4. FMA-pipe-bound target ~16-18us.
// ---------------------------------------------------------------------------
__global__ void __launch_bounds__(512) k1_proj(
    const float* __restrict__ en, const float* __restrict__ de,
    const float* __restrict__ w_en, const float* __restrict__ w_de)
{
    __shared__ float  s_in[32*ND];       // 32 input rows, 32KB
    __shared__ float4 s_w[2][16*64];     // 2 stages x (16 d x 64 u-groups), 2x16KB
    int bb = blockIdx.x;
    bool isA = bb < 64;
    int rb = (isA ? bb : bb - 64) * 32;            // row base in [0,2048)
    const float* in = isA ? en : de;
    const float* w  = isA ? w_en : w_de;
    float* out      = isA ? g_ae : g_ad;
    int tid = threadIdx.x;

    // cooperative load of 32 input rows (8192 floats = 2048 float4)
    {
        const float4* in4 = (const float4*)(in + rb*ND);
        float4* s4 = (float4*)s_in;
        #pragma unroll
        for (int i = 0; i < 4; i++)
            s4[tid + i*512] = in4[tid + i*512];
    }

    const float4* w4 = (const float4*)w;     // [d*64 + ug]

    // prologue: stage 0 = d rows 0..15 -> flat float4 idx 0..1023
    float4 q0 = w4[tid];
    float4 q1 = w4[tid + 512];
    s_w[0][tid]       = q0;
    s_w[0][tid + 512] = q1;
    __syncthreads();

    int tx = tid & 63;        // u-group of 4
    int ty = tid >> 6;        // 0..7 -> rows ty*4..ty*4+3 (warp-uniform)
    const float* srow = s_in + ty*4*ND;

    float4 a0 = make_float4(0.f,0.f,0.f,0.f);
    float4 a1 = a0, a2 = a0, a3 = a0;

    for (int st = 0; st < 16; st++){
        int cur = st & 1;
        if (st < 15){
            q0 = w4[(st+1)*1024 + tid];
            q1 = w4[(st+1)*1024 + tid + 512];
        }
        #pragma unroll
        for (int dd = 0; dd < 16; dd++){
            int d = st*16 + dd;
            float4 wv = s_w[cur][dd*64 + tx];
            float x0 = srow[0*ND + d];
            float x1 = srow[1*ND + d];
            float x2 = srow[2*ND + d];
            float x3 = srow[3*ND + d];
            a0.x = fmaf(x0, wv.x, a0.x); a0.y = fmaf(x0, wv.y, a0.y);
            a0.z = fmaf(x0, wv.z, a0.z); a0.w = fmaf(x0, wv.w, a0.w);
            a1.x = fmaf(x1, wv.x, a1.x); a1.y = fmaf(x1, wv.y, a1.y);
            a1.z = fmaf(x1, wv.z, a1.z); a1.w = fmaf(x1, wv.w, a1.w);
            a2.x = fmaf(x2, wv.x, a2.x); a2.y = fmaf(x2, wv.y, a2.y);
            a2.z = fmaf(x2, wv.z, a2.z); a2.w = fmaf(x2, wv.w, a2.w);
            a3.x = fmaf(x3, wv.x, a3.x); a3.y = fmaf(x3, wv.y, a3.y);
            a3.z = fmaf(x3, wv.z, a3.z); a3.w = fmaf(x3, wv.w, a3.w);
        }
        if (st < 15){
            int nxt = cur ^ 1;
            s_w[nxt][tid]       = q0;
            s_w[nxt][tid + 512] = q1;
        }
        __syncthreads();
    }

    int r = rb + ty*4;
    ((float4*)(out + (r+0)*NU))[tx] = a0;
    ((float4*)(out + (r+1)*NU))[tx] = a1;
    ((float4*)(out + (r+2)*NU))[tx] = a2;
    ((float4*)(out + (r+3)*NU))[tx] = a3;
}

// ---------------------------------------------------------------------------
// K2 (unchanged — at the MUFU throughput floor ~31us)
// ---------------------------------------------------------------------------
__global__ void __launch_bounds__(256) k2_mu(const float* __restrict__ nu)
{
    __shared__ float s_mu[4][256];
    int blk  = blockIdx.x;
    int b    = blk >> 6;              // 64 blocks per batch
    int s0   = (blk & 63) * 4;
    int lane = threadIdx.x & 31;
    int w    = threadIdx.x >> 5;

    float nur[8], adr0[8], adr1[8], adr2[8], adr3[8];
    #pragma unroll
    for (int k = 0; k < 8; k++) nur[k] = nu[lane + 32*k];
    const float* adb = g_ad + (b*NT + s0)*NU;
    #pragma unroll
    for (int k = 0; k < 8; k++){
        int u = lane + 32*k;
        adr0[k] = adb[0*NU + u];
        adr1[k] = adb[1*NU + u];
        adr2[k] = adb[2*NU + u];
        adr3[k] = adb[3*NU + u];
    }
    const float* aeb = g_ae + b*NT*NU;

    for (int ti = 0; ti < 32; ti++){
        int t = ti*8 + w;
        const float* aet = aeb + t*NU;
        float a0=0.f, a1=0.f, a2=0.f, a3=0.f;
        #pragma unroll
        for (int k = 0; k < 8; k++){
            float a = aet[lane + 32*k];
            a0 = fmaf(tanh_fast(adr0[k] + a), nur[k], a0);
            a1 = fmaf(tanh_fast(adr1[k] + a), nur[k], a1);
            a2 = fmaf(tanh_fast(adr2[k] + a), nur[k], a2);
            a3 = fmaf(tanh_fast(adr3[k] + a), nur[k], a3);
        }
        #pragma unroll
        for (int off = 16; off; off >>= 1){
            a0 += __shfl_xor_sync(0xffffffffu, a0, off);
            a1 += __shfl_xor_sync(0xffffffffu, a1, off);
            a2 += __shfl_xor_sync(0xffffffffu, a2, off);
            a3 += __shfl_xor_sync(0xffffffffu, a3, off);
        }
        if (lane == 0){
            s_mu[0][t] = a0; s_mu[1][t] = a1;
            s_mu[2][t] = a2; s_mu[3][t] = a3;
        }
    }
    __syncthreads();

    if (w < 4){
        int s = w;
        float v[8];
        float m = -1e30f;
        #pragma unroll
        for (int j = 0; j < 8; j++){ v[j] = s_mu[s][lane + 32*j]; m = fmaxf(m, v[j]); }
        #pragma unroll
        for (int off = 16; off; off >>= 1) m = fmaxf(m, __shfl_xor_sync(0xffffffffu, m, off));
        float sum = 0.f;
        #pragma unroll
        for (int j = 0; j < 8; j++){ v[j] = __expf(v[j] - m); sum += v[j]; }
        #pragma unroll
        for (int off = 16; off; off >>= 1) sum += __shfl_xor_sync(0xffffffffu, sum, off);
        float inv = 1.0f / sum;
        float* arow = g_alphas + (b*NT + s0 + s)*NT;
        #pragma unroll
        for (int j = 0; j < 8; j++) arow[lane + 32*j] = v[j] * inv;
        if (lane == 0) g_maxmu[b*NT + s0 + s] = m;
    }
}

// ---------------------------------------------------------------------------
// K3 (unchanged, ~3us)
// ---------------------------------------------------------------------------
__global__ void __launch_bounds__(256) k3_hhat(const float* __restrict__ de)
{
    __shared__ float s_ma[256];
    __shared__ float s_red[8];
    int b = blockIdx.x;
    int tid = threadIdx.x, lane = tid & 31, w = tid >> 5;

    float v = g_maxmu[b*NT + tid];
    float m = v;
    #pragma unroll
    for (int off = 16; off; off >>= 1) m = fmaxf(m, __shfl_xor_sync(0xffffffffu, m, off));
    if (lane == 0) s_red[w] = m;
    __syncthreads();
    m = s_red[0];
    #pragma unroll
    for (int i = 1; i < 8; i++) m = fmaxf(m, s_red[i]);
    __syncthreads();

    float e = __expf(v - m);
    float psum = e;
    #pragma unroll
    for (int off = 16; off; off >>= 1) psum += __shfl_xor_sync(0xffffffffu, psum, off);
    if (lane == 0) s_red[w] = psum;
    __syncthreads();
    float tot = 0.f;
    #pragma unroll
    for (int i = 0; i < 8; i++) tot += s_red[i];
    s_ma[tid] = e / tot;
    __syncthreads();

    int d = tid;
    const float* deb = de + b*NT*ND;
    float acc = 0.f;
    #pragma unroll 4
    for (int s = 0; s < NT; s++) acc = fmaf(deb[s*ND + d], s_ma[s], acc);
    g_hhat[b*ND + d] = acc;
}

// ---------------------------------------------------------------------------
// K4 v4: sum_en[b,s,:] = alphas[b,s,:] @ en[b]; assemble output concat.
// grid 128: block = (b, 16 s rows). 512 threads (4 warps/SMSP).
// Per thread: 2 s x 4 d register tile. en double-buffered through SMEM in
// 8-t stages (1 LDG.128 per thread per stage, bulk-issued).
// ---------------------------------------------------------------------------
__global__ void __launch_bounds__(512) k4_out(
    const float* __restrict__ en, const float* __restrict__ de,
    float* __restrict__ out)
{
    __shared__ float  s_a[16*NT];        // alphas tile [s][t], 16KB
    __shared__ float4 s_en[2][512];      // 2 stages x (8 t-rows x 64 float4), 16KB
    int blk = blockIdx.x;
    int b   = blk >> 4;
    int s0  = (blk & 15) * 16;
    int tid = threadIdx.x;

    // cooperative load of 16 alpha rows (4096 floats = 1024 float4)
    {
        const float4* ab = (const float4*)(g_alphas + (b*NT + s0)*NT);
        float4* sa4 = (float4*)s_a;
        sa4[tid]       = ab[tid];
        sa4[tid + 512] = ab[tid + 512];
    }

    const float4* en4 = (const float4*)(en + b*NT*ND);

    // prologue: stage 0 (t rows 0..7 = flat float4 indices 0..511)
    float4 p0 = en4[tid];
    s_en[0][tid] = p0;
    __syncthreads();

    int tx = tid & 63;        // d-group of 4
    int ty = tid >> 6;        // 0..7 -> s rows ty*2, ty*2+1 (warp-uniform)
    const float* arow = s_a + ty*2*NT;

    float4 c0 = make_float4(0.f,0.f,0.f,0.f);
    float4 c1 = c0;

    for (int st = 0; st < 32; st++){
        int cur = st & 1;
        if (st < 31) p0 = en4[(st+1)*512 + tid];
        #pragma unroll
        for (int j = 0; j < 8; j++){
            int t = st*8 + j;
            float4 e = s_en[cur][j*64 + tx];
            float x0 = arow[0*NT + t];
            float x1 = arow[1*NT + t];
            c0.x = fmaf(x0, e.x, c0.x); c0.y = fmaf(x0, e.y, c0.y);
            c0.z = fmaf(x0, e.z, c0.z); c0.w = fmaf(x0, e.w, c0.w);
            c1.x = fmaf(x1, e.x, c1.x); c1.y = fmaf(x1, e.y, c1.y);
            c1.z = fmaf(x1, e.z, c1.z); c1.w = fmaf(x1, e.w, c1.w);
        }
        if (st < 31) s_en[cur ^ 1][tid] = p0;
        __syncthreads();
    }

    float4 hh = ((const float4*)(g_hhat + b*ND))[tx];

    #pragma unroll
    for (int j = 0; j < 2; j++){
        int row = b*NT + s0 + ty*2 + j;
        float4 dv = ((const float4*)(de + row*ND))[tx];
        float4 cs = (j == 0) ? c0 : c1;
        float4* o = (float4*)(out + (size_t)row * (4*ND));
        o[0*64 + tx] = dv;
        o[1*64 + tx] = cs;
        o[2*64 + tx] = make_float4(dv.x*cs.x, dv.y*cs.y, dv.z*cs.z, dv.w*cs.w);
        o[3*64 + tx] = make_float4(dv.x*hh.x, dv.y*hh.y, dv.z*hh.z, dv.w*hh.w);
    }
}

extern "C" void kernel_launch(void* const* d_in, const int* in_sizes, int n_in,
                              void* d_out, int out_size)
{
    const float* en   = (const float*)d_in[0];
    const float* de   = (const float*)d_in[1];
    const float* w_en = (const float*)d_in[2];
    const float* w_de = (const float*)d_in[3];
    const float* nu   = (const float*)d_in[4];
    float* out = (float*)d_out;

    k1_proj<<<128, 512>>>(en, de, w_en, w_de);
    k2_mu  <<<512, 256>>>(nu);
    k3_hhat<<<NB,  256>>>(de);
    k4_out <<<128, 512>>>(en, de, out);
}